// round 15
// baseline (speedup 1.0000x reference)
#include <cuda_runtime.h>
#include <math.h>

#define Hn   512
#define Bn   1024
#define Vn   1024
#define Tn   64
#define GENn 100
#define GPAD 104            // GEN padded for unroll (rows 100..103 zero)
#define W1ROWS (Hn + 8)     // 520: 8 pad rows so z-phase ring prefetch never OOB
#define W2ROWS 112          // GEN padded + prefetch slack (rows 100..111 zero)

// ---------------- persistent device scratch (no allocs allowed) ----------------
__device__ float d_Wt[Hn * 4 * Hn];         // [512][2048]  W_hh permuted+transposed
__device__ float d_W1t[W1ROWS * 128];       // [520][128]   W1^T padded
__device__ float d_W2t[W2ROWS * Vn];        // [112][1024]  W2^T padded
__device__ float d_Wih_t[Vn * 4 * Hn];      // [1024][2048] W_ih^T permuted: [v][p], p=j*4+g
__device__ float d_bias[4 * Hn];            // [2048] b_ih+b_hh permuted
__device__ float d_gates[Bn * 4 * Hn];      // [1024][2048] gate preactivations
__device__ float d_h[2][Bn * Hn];           // ping-pong hidden state
__device__ float d_c[Bn * Hn];              // cell state
__device__ int   d_tok[Bn];                 // current token per batch row

// ---------------- smem layouts (union for the fused kernel) ----------------
struct GemmSmem {
    float As[16][128];
    float Bs[16][128];
};
struct HeadSmem {
    float hs[8][512];
    float zpart[16][128];
    float zs[GPAD][8];
    float red[8][16];
    int   redi[8][16];
    float gmaxS[8];
};
union FusedSmem {
    GemmSmem g;
    HeadSmem h;
};

// ---------------- weight re-layout ----------------
__global__ void prep_kernel(const float* __restrict__ W_hh,
                            const float* __restrict__ W1,
                            const float* __restrict__ W2,
                            const float* __restrict__ W_ih,
                            const float* __restrict__ b_ih,
                            const float* __restrict__ b_hh) {
    int id = blockIdx.x * blockDim.x + threadIdx.x;
    const int n1 = Hn * 4 * Hn;             // 1048576
    const int n2 = W1ROWS * 128;            // 66560
    const int n3 = W2ROWS * Vn;             // 114688
    const int n4 = Vn * 4 * Hn;             // 2097152
    const int n5 = 4 * Hn;                  // 2048
    if (id < n1) {
        int k = id >> 11, p = id & 2047;
        int j = p >> 2, g = p & 3;
        d_Wt[id] = W_hh[(g * Hn + j) * Hn + k];
    } else if (id < n1 + n2) {
        int i = id - n1;
        int k = i >> 7, j = i & 127;
        d_W1t[i] = (j < GENn && k < Hn) ? W1[j * Hn + k] : 0.0f;
    } else if (id < n1 + n2 + n3) {
        int i = id - n1 - n2;
        int k = i >> 10, v = i & 1023;
        d_W2t[i] = (k < GENn) ? W2[v * GENn + k] : 0.0f;
    } else if (id < n1 + n2 + n3 + n4) {
        int i = id - n1 - n2 - n3;
        int v = i >> 11, p = i & 2047;
        int j = p >> 2, g = p & 3;
        d_Wih_t[i] = W_ih[(size_t)(g * Hn + j) * Vn + v];
    } else if (id < n1 + n2 + n3 + n4 + n5) {
        int p = id - n1 - n2 - n3 - n4;
        int j = p >> 2, g = p & 3;
        d_bias[p] = b_ih[g * Hn + j] + b_hh[g * Hn + j];
    }
}

// ---------------- h0/c0 expansion + initial token ----------------
__global__ void init_kernel(const float* __restrict__ input,
                            const float* __restrict__ Wh, const float* __restrict__ bh,
                            const float* __restrict__ Wc, const float* __restrict__ bc,
                            const float* __restrict__ onehots) {
    int id = blockIdx.x * blockDim.x + threadIdx.x;
    if (id < Bn * Hn) {
        int b = id / Hn, j = id % Hn;
        float x = input[b];
        d_h[0][id] = x * Wh[j] + bh[j];
        d_c[id]    = x * Wc[j] + bc[j];
    } else {
        int i2 = id - Bn * Hn;
        if (i2 < Bn * Vn) {
            int b = i2 >> 10, v = i2 & 1023;
            if (onehots[(size_t)b * (Tn * Vn) + v] > 0.5f) d_tok[b] = v;
        }
    }
}

// ---------------- gemm body: 512 threads, 128x128 tile, 4x8 micro-tile ----------------
__device__ __forceinline__ void gemm_body(GemmSmem& sm, int nxt, int blk) {
    const float* hin = d_h[nxt];
    int tid = threadIdx.x;
    int tx = tid & 15, ty = tid >> 4;       // tx: 16 col-groups of 8; ty: 32 row-groups of 4
    int bn0 = (blk & 15) * 128;             // p base
    int bm0 = (blk >> 4) * 128;             // b base

    float acc[4][8];
#pragma unroll
    for (int r = 0; r < 4; r++)
#pragma unroll
        for (int q = 0; q < 8; q++) acc[r][q] = 0.0f;

    for (int k0 = 0; k0 < Hn; k0 += 16) {
        {   // A tile: 512 float4, one per thread, transposed store
            int row = tid >> 2;
            int c4  = (tid & 3) * 4;
            float4 v = *(const float4*)&hin[(size_t)(bm0 + row) * Hn + k0 + c4];
            sm.As[c4 + 0][row] = v.x; sm.As[c4 + 1][row] = v.y;
            sm.As[c4 + 2][row] = v.z; sm.As[c4 + 3][row] = v.w;
        }
        {   // B tile: 512 float4, one per thread
            int row = tid >> 5;
            int c4  = (tid & 31) * 4;
            *(float4*)&sm.Bs[row][c4] = *(const float4*)&d_Wt[(size_t)(k0 + row) * 2048 + bn0 + c4];
        }
        __syncthreads();
#pragma unroll
        for (int kk = 0; kk < 16; kk++) {
            float a[4], bb[8];
            *(float4*)&a[0]  = *(const float4*)&sm.As[kk][ty * 4];
            *(float4*)&bb[0] = *(const float4*)&sm.Bs[kk][tx * 8];
            *(float4*)&bb[4] = *(const float4*)&sm.Bs[kk][tx * 8 + 4];
#pragma unroll
            for (int r = 0; r < 4; r++)
#pragma unroll
                for (int q = 0; q < 8; q++) acc[r][q] += a[r] * bb[q];
        }
        __syncthreads();
    }

    int p0 = bn0 + tx * 8;
#pragma unroll
    for (int r = 0; r < 4; r++) {
        int b_idx = bm0 + ty * 4 + r;
        float* dst = &d_gates[(size_t)b_idx * 2048 + p0];
        *(float4*)&dst[0] = make_float4(acc[r][0], acc[r][1], acc[r][2], acc[r][3]);
        *(float4*)&dst[4] = make_float4(acc[r][4], acc[r][5], acc[r][6], acc[r][7]);
    }
}

// ---------------- head body (v3, measured best) ----------------
__device__ __forceinline__ void head_body(HeadSmem& sm, int nxt,
                                          const float* __restrict__ b1,
                                          const float* __restrict__ b2,
                                          float* __restrict__ out, int blk) {
    const float* __restrict__ h = d_h[nxt];
    int tid = threadIdx.x;
    int w = tid >> 5, l = tid & 31;
    int b0 = blk * 8;

    {
        const float4* src = (const float4*)(h + (size_t)b0 * Hn);
        float4* dst = (float4*)sm.hs;
        dst[tid]       = src[tid];
        dst[tid + 512] = src[tid + 512];
    }
    __syncthreads();

    // ---- z partials: 8-deep LDG ring ----
    {
        int r  = w & 7;
        int kh = w >> 3;
        const float4* w1p = (const float4*)d_W1t + (size_t)kh * 256 * 32 + l;
        const float*  hrow = sm.hs[r] + kh * 256;
        float4 ring[8];
#pragma unroll
        for (int i = 0; i < 8; i++) ring[i] = w1p[(size_t)i * 32];
        float4 acc = make_float4(0.f, 0.f, 0.f, 0.f);
#pragma unroll 8
        for (int k = 0; k < 256; k++) {
            float4 cur = ring[k & 7];
            ring[k & 7] = w1p[(size_t)(k + 8) * 32];   // pad rows keep in-bounds
            float hv = hrow[k];
            acc.x += hv * cur.x; acc.y += hv * cur.y;
            acc.z += hv * cur.z; acc.w += hv * cur.w;
        }
        *(float4*)&sm.zpart[w][4 * l] = acc;
    }
    __syncthreads();

    for (int idx = tid; idx < 8 * 128; idx += 512) {
        int r = idx >> 7, j = idx & 127;
        if (j < GPAD) {
            float v = 0.0f;
            if (j < GENn)
                v = fmaxf(sm.zpart[r][j] + sm.zpart[r + 8][j] + b1[j], 0.0f);
            sm.zs[j][r] = v;
        }
    }
    __syncthreads();

    // ---- logits ----
    float lg0[8], lg1[8];
#pragma unroll
    for (int r = 0; r < 8; r++) { lg0[r] = 0.f; lg1[r] = 0.f; }
    {
        const float2* w2p = (const float2*)d_W2t + w * 32 + l;
        float2 p0[4], p1[4];
#pragma unroll
        for (int i = 0; i < 4; i++) p0[i] = w2p[(size_t)i * 512];
#pragma unroll
        for (int i = 0; i < 4; i++) p1[i] = w2p[(size_t)(4 + i) * 512];
        for (int k0 = 0; k0 < GPAD; k0 += 4) {
            float2 nb[4];
#pragma unroll
            for (int i = 0; i < 4; i++) nb[i] = w2p[(size_t)(k0 + 8 + i) * 512];
#pragma unroll
            for (int i = 0; i < 4; i++) {
                int k = k0 + i;
                float zv[8];
                *(float4*)&zv[0] = *(const float4*)&sm.zs[k][0];
                *(float4*)&zv[4] = *(const float4*)&sm.zs[k][4];
#pragma unroll
                for (int r = 0; r < 8; r++) {
                    lg0[r] += p0[i].x * zv[r];
                    lg1[r] += p0[i].y * zv[r];
                }
            }
#pragma unroll
            for (int i = 0; i < 4; i++) { p0[i] = p1[i]; p1[i] = nb[i]; }
        }
        float bx = b2[w * 64 + 2 * l], by = b2[w * 64 + 2 * l + 1];
#pragma unroll
        for (int r = 0; r < 8; r++) { lg0[r] += bx; lg1[r] += by; }
    }

    int vbase = w * 64 + 2 * l;
#pragma unroll
    for (int r = 0; r < 8; r++) {
        float m; int a;
        if (lg1[r] > lg0[r]) { m = lg1[r]; a = vbase + 1; }
        else                 { m = lg0[r]; a = vbase;     }
#pragma unroll
        for (int o = 16; o > 0; o >>= 1) {
            float m2 = __shfl_xor_sync(0xffffffffu, m, o);
            int   a2 = __shfl_xor_sync(0xffffffffu, a, o);
            if (m2 > m || (m2 == m && a2 < a)) { m = m2; a = a2; }
        }
        if (l == 0) { sm.red[r][w] = m; sm.redi[r][w] = a; }
    }
    __syncthreads();

    if (tid < 8) {
        float m = sm.red[tid][0]; int a = sm.redi[tid][0];
#pragma unroll
        for (int ww = 1; ww < 16; ww++) {
            float m2 = sm.red[tid][ww]; int a2 = sm.redi[tid][ww];
            if (m2 > m || (m2 == m && a2 < a)) { m = m2; a = a2; }
        }
        d_tok[b0 + tid] = a;
        sm.gmaxS[tid] = m;
    }
    __syncthreads();

    float gmax[8];
#pragma unroll
    for (int r = 0; r < 8; r++) gmax[r] = sm.gmaxS[r];

#pragma unroll
    for (int r = 0; r < 8; r++) {
        float s = expf(lg0[r] - gmax[r]) + expf(lg1[r] - gmax[r]);
#pragma unroll
        for (int o = 16; o > 0; o >>= 1) s += __shfl_xor_sync(0xffffffffu, s, o);
        if (l == 0) sm.red[r][w] = s;
    }
    __syncthreads();

    float logZ[8];
#pragma unroll
    for (int r = 0; r < 8; r++) {
        float s = 0.0f;
#pragma unroll
        for (int ww = 0; ww < 16; ww++) s += sm.red[r][ww];
        logZ[r] = logf(s);
    }

#pragma unroll
    for (int r = 0; r < 8; r++) {
        float2 o2;
        o2.x = lg0[r] - gmax[r] - logZ[r];
        o2.y = lg1[r] - gmax[r] - logZ[r];
        *(float2*)&out[(size_t)(b0 + r) * Vn + vbase] = o2;
    }
}

// ---------------- fused: blocks 0-127 gemm(t+1), blocks 128-255 head(t) ----------------
__global__ __launch_bounds__(512) void fused_kernel(
    int nxt,
    const float* __restrict__ b1,
    const float* __restrict__ b2,
    float* __restrict__ out) {
    __shared__ FusedSmem sm;
    if (blockIdx.x < 128) gemm_body(sm.g, nxt, blockIdx.x);
    else                  head_body(sm.h, nxt, b1, b2, out, blockIdx.x - 128);
}

// ---------------- standalone wrappers (first gemm, last head) ----------------
__global__ __launch_bounds__(512) void gemm_kernel(int nxt) {
    __shared__ GemmSmem sm;
    gemm_body(sm, nxt, blockIdx.x);
}
__global__ __launch_bounds__(512) void head_kernel(
    int nxt,
    const float* __restrict__ b1,
    const float* __restrict__ b2,
    float* __restrict__ out) {
    __shared__ HeadSmem sm;
    head_body(sm, nxt, b1, b2, out, blockIdx.x);
}

// ---------------- cell: gates + Wih_t[tok] gather + LSTM nonlinearity ----------------
__global__ __launch_bounds__(256) void cell_kernel(int cur) {
    int id = blockIdx.x * 256 + threadIdx.x;     // 0 .. 524287
    int b = id >> 9, j = id & 511;
    int tk = d_tok[b];
    float4 g4 = *(const float4*)&d_gates[(size_t)b * 2048 + j * 4];
    float4 w4 = *(const float4*)&d_Wih_t[(size_t)tk * 2048 + j * 4];
    float4 bi = *(const float4*)&d_bias[j * 4];
    float gi = g4.x + w4.x + bi.x;
    float gf = g4.y + w4.y + bi.y;
    float gg = g4.z + w4.z + bi.z;
    float go = g4.w + w4.w + bi.w;
    float si = 1.0f / (1.0f + expf(-gi));
    float sf = 1.0f / (1.0f + expf(-gf));
    float so = 1.0f / (1.0f + expf(-go));
    float tg = tanhf(gg);
    int idx = b * Hn + j;
    float cn = sf * d_c[idx] + si * tg;
    d_c[idx] = cn;
    d_h[cur ^ 1][idx] = so * tanhf(cn);
}

// ---------------- launch: single stream, overlap via fused kernel ----------------
extern "C" void kernel_launch(void* const* d_in, const int* in_sizes, int n_in,
                              void* d_out, int out_size) {
    (void)out_size;
    int off = (n_in >= 16 && in_sizes[3] == 1) ? 4 : 3;
    const float* input   = (const float*)d_in[0];
    const float* onehots = (const float*)d_in[1];
    const float* Wh   = (const float*)d_in[off + 0];
    const float* bh   = (const float*)d_in[off + 1];
    const float* Wc   = (const float*)d_in[off + 2];
    const float* bc   = (const float*)d_in[off + 3];
    const float* W_ih = (const float*)d_in[off + 4];
    const float* W_hh = (const float*)d_in[off + 5];
    const float* b_ih = (const float*)d_in[off + 6];
    const float* b_hh = (const float*)d_in[off + 7];
    const float* W1   = (const float*)d_in[off + 8];
    const float* b1   = (const float*)d_in[off + 9];
    const float* W2   = (const float*)d_in[off + 10];
    const float* b2   = (const float*)d_in[off + 11];
    float* out = (float*)d_out;

    const int prepN = Hn * 4 * Hn + W1ROWS * 128 + W2ROWS * Vn + Vn * 4 * Hn + 4 * Hn;
    prep_kernel<<<(prepN + 255) / 256, 256>>>(W_hh, W1, W2, W_ih, b_ih, b_hh);

    const int initN = Bn * Hn + Bn * Vn;
    init_kernel<<<(initN + 255) / 256, 256>>>(input, Wh, bh, Wc, bc, onehots);

    // t=0: gemm_0 (reads h_0 = d_h[0]) ; cell_0 (tok from init) -> h_1 in d_h[1]
    gemm_kernel<<<128, 512>>>(0);
    cell_kernel<<<2048, 256>>>(0);

    // steps: fused(head_t || gemm_{t+1}) then cell_{t+1}
    for (int t = 0; t < Tn - 1; t++) {
        int nxt = (t + 1) & 1;                 // h_{t+1} buffer
        fused_kernel<<<256, 512>>>(nxt, b1, b2, out + (size_t)t * Bn * Vn);
        cell_kernel<<<2048, 256>>>(nxt);       // writes h_{t+2} = d_h[nxt^1]
    }
    // final head_63 reads h_64 = d_h[(Tn)&1] = d_h[0]
    head_kernel<<<128, 512>>>(Tn & 1, b1, b2, out + (size_t)(Tn - 1) * Bn * Vn);
}

// round 16
// speedup vs baseline: 1.6048x; 1.6048x over previous
#include <cuda_runtime.h>
#include <math.h>

#define Hn   512
#define Bn   1024
#define Vn   1024
#define Tn   64
#define GENn 100
#define GPAD 104            // GEN padded for unroll (rows 100..103 zero)
#define W1ROWS (Hn + 8)     // 520: 8 pad rows so z-phase ring prefetch never OOB
#define W2ROWS 112          // GEN padded + prefetch slack (rows 100..111 zero)

// ---------------- persistent device scratch (no allocs allowed) ----------------
__device__ float d_Wt[Hn * 4 * Hn];         // [512][2048]  W_hh permuted+transposed
__device__ float d_W1t[W1ROWS * 128];       // [520][128]   W1^T padded
__device__ float d_W2t[W2ROWS * Vn];        // [112][1024]  W2^T padded
__device__ float d_Wih_t[Vn * 4 * Hn];      // [1024][2048] W_ih^T permuted: [v][p], p=j*4+g
__device__ float d_bias[4 * Hn];            // [2048] b_ih+b_hh permuted
__device__ float d_h[2][Bn * Hn];           // ping-pong hidden state
__device__ float d_c[Bn * Hn];              // cell state
__device__ int   d_tok[Bn];                 // current token per batch row
__device__ unsigned int d_ctr;              // head-block completion counter

// ---------------- smem layouts (union for the fused kernel) ----------------
struct GemmSmem {
    float As[16][128];
    float Bs[16][128];
};
struct HeadSmem {
    float hs[8][512];
    float zpart[16][128];
    float zs[GPAD][8];
    float red[8][16];
    int   redi[8][16];
    float gmaxS[8];
};
union FusedSmem {
    GemmSmem g;
    HeadSmem h;
};

// ---------------- weight re-layout ----------------
__global__ void prep_kernel(const float* __restrict__ W_hh,
                            const float* __restrict__ W1,
                            const float* __restrict__ W2,
                            const float* __restrict__ W_ih,
                            const float* __restrict__ b_ih,
                            const float* __restrict__ b_hh) {
    int id = blockIdx.x * blockDim.x + threadIdx.x;
    const int n1 = Hn * 4 * Hn;             // 1048576
    const int n2 = W1ROWS * 128;            // 66560
    const int n3 = W2ROWS * Vn;             // 114688
    const int n4 = Vn * 4 * Hn;             // 2097152
    const int n5 = 4 * Hn;                  // 2048
    if (id < n1) {
        int k = id >> 11, p = id & 2047;
        int j = p >> 2, g = p & 3;
        d_Wt[id] = W_hh[(g * Hn + j) * Hn + k];
    } else if (id < n1 + n2) {
        int i = id - n1;
        int k = i >> 7, j = i & 127;
        d_W1t[i] = (j < GENn && k < Hn) ? W1[j * Hn + k] : 0.0f;
    } else if (id < n1 + n2 + n3) {
        int i = id - n1 - n2;
        int k = i >> 10, v = i & 1023;
        d_W2t[i] = (k < GENn) ? W2[v * GENn + k] : 0.0f;
    } else if (id < n1 + n2 + n3 + n4) {
        int i = id - n1 - n2 - n3;
        int v = i >> 11, p = i & 2047;
        int j = p >> 2, g = p & 3;
        d_Wih_t[i] = W_ih[(size_t)(g * Hn + j) * Vn + v];
    } else if (id < n1 + n2 + n3 + n4 + n5) {
        int p = id - n1 - n2 - n3 - n4;
        int j = p >> 2, g = p & 3;
        d_bias[p] = b_ih[g * Hn + j] + b_hh[g * Hn + j];
    }
}

// ---------------- h0/c0 expansion + initial token + counter reset ----------------
__global__ void init_kernel(const float* __restrict__ input,
                            const float* __restrict__ Wh, const float* __restrict__ bh,
                            const float* __restrict__ Wc, const float* __restrict__ bc,
                            const float* __restrict__ onehots) {
    int id = blockIdx.x * blockDim.x + threadIdx.x;
    if (id == 0) d_ctr = 0u;
    if (id < Bn * Hn) {
        int b = id / Hn, j = id % Hn;
        float x = input[b];
        d_h[0][id] = x * Wh[j] + bh[j];
        d_c[id]    = x * Wc[j] + bc[j];
    } else {
        int i2 = id - Bn * Hn;
        if (i2 < Bn * Vn) {
            int b = i2 >> 10, v = i2 & 1023;
            if (onehots[(size_t)b * (Tn * Vn) + v] > 0.5f) d_tok[b] = v;
        }
    }
}

// ---------------- gemm + in-register cell epilogue (waits for tok via d_ctr) ----------------
__device__ __forceinline__ void gemm_cell_body(GemmSmem& sm, int nxt, int target, int blk) {
    const float* hin  = d_h[nxt];
    float*       hout = d_h[nxt ^ 1];
    int tid = threadIdx.x;
    int tx = tid & 15, ty = tid >> 4;       // 16 col-groups of 8 ; 32 row-groups of 4
    int bn0 = (blk & 15) * 128;             // p base
    int bm0 = (blk >> 4) * 128;             // b base

    float acc[4][8];
#pragma unroll
    for (int r = 0; r < 4; r++)
#pragma unroll
        for (int q = 0; q < 8; q++) acc[r][q] = 0.0f;

    for (int k0 = 0; k0 < Hn; k0 += 16) {
        {   // A tile: 512 float4, one per thread, transposed store
            int row = tid >> 2;
            int c4  = (tid & 3) * 4;
            float4 v = *(const float4*)&hin[(size_t)(bm0 + row) * Hn + k0 + c4];
            sm.As[c4 + 0][row] = v.x; sm.As[c4 + 1][row] = v.y;
            sm.As[c4 + 2][row] = v.z; sm.As[c4 + 3][row] = v.w;
        }
        {   // B tile: 512 float4, one per thread
            int row = tid >> 5;
            int c4  = (tid & 31) * 4;
            *(float4*)&sm.Bs[row][c4] = *(const float4*)&d_Wt[(size_t)(k0 + row) * 2048 + bn0 + c4];
        }
        __syncthreads();
#pragma unroll
        for (int kk = 0; kk < 16; kk++) {
            float a[4], bb[8];
            *(float4*)&a[0]  = *(const float4*)&sm.As[kk][ty * 4];
            *(float4*)&bb[0] = *(const float4*)&sm.Bs[kk][tx * 8];
            *(float4*)&bb[4] = *(const float4*)&sm.Bs[kk][tx * 8 + 4];
#pragma unroll
            for (int r = 0; r < 4; r++)
#pragma unroll
                for (int q = 0; q < 8; q++) acc[r][q] += a[r] * bb[q];
        }
        __syncthreads();
    }

    // wait for head blocks of this launch to publish tok (target=0 -> no wait)
    if (tid == 0) {
        while ((int)atomicAdd(&d_ctr, 0u) < target) __nanosleep(64);
    }
    __syncthreads();

    // in-register cell epilogue: + Wih_t[tok] + bias -> LSTM -> h/c
    int p0 = bn0 + tx * 8;
    int j0 = p0 >> 2;                       // covers j0, j0+1
    float4 bi0 = *(const float4*)&d_bias[p0];
    float4 bi1 = *(const float4*)&d_bias[p0 + 4];
#pragma unroll
    for (int r = 0; r < 4; r++) {
        int b_idx = bm0 + ty * 4 + r;
        int tk = __ldcg(&d_tok[b_idx]);     // L2 read: fresh across the in-kernel sync
        const float* wr = &d_Wih_t[(size_t)tk * 2048 + p0];
        float4 w0 = *(const float4*)&wr[0];
        float4 w1 = *(const float4*)&wr[4];
        {   // j = j0
            float gi = acc[r][0] + w0.x + bi0.x;
            float gf = acc[r][1] + w0.y + bi0.y;
            float gg = acc[r][2] + w0.z + bi0.z;
            float go = acc[r][3] + w0.w + bi0.w;
            float si = 1.0f / (1.0f + expf(-gi));
            float sf = 1.0f / (1.0f + expf(-gf));
            float so = 1.0f / (1.0f + expf(-go));
            float tg = tanhf(gg);
            int idx = b_idx * Hn + j0;
            float cn = sf * d_c[idx] + si * tg;
            d_c[idx] = cn;
            hout[idx] = so * tanhf(cn);
        }
        {   // j = j0 + 1
            float gi = acc[r][4] + w1.x + bi1.x;
            float gf = acc[r][5] + w1.y + bi1.y;
            float gg = acc[r][6] + w1.z + bi1.z;
            float go = acc[r][7] + w1.w + bi1.w;
            float si = 1.0f / (1.0f + expf(-gi));
            float sf = 1.0f / (1.0f + expf(-gf));
            float so = 1.0f / (1.0f + expf(-go));
            float tg = tanhf(gg);
            int idx = b_idx * Hn + j0 + 1;
            float cn = sf * d_c[idx] + si * tg;
            d_c[idx] = cn;
            hout[idx] = so * tanhf(cn);
        }
    }
}

// ---------------- head body (v3) + early tok publication ----------------
__device__ __forceinline__ void head_body(HeadSmem& sm, int nxt,
                                          const float* __restrict__ b1,
                                          const float* __restrict__ b2,
                                          float* __restrict__ out, int blk) {
    const float* __restrict__ h = d_h[nxt];
    int tid = threadIdx.x;
    int w = tid >> 5, l = tid & 31;
    int b0 = blk * 8;

    {
        const float4* src = (const float4*)(h + (size_t)b0 * Hn);
        float4* dst = (float4*)sm.hs;
        dst[tid]       = src[tid];
        dst[tid + 512] = src[tid + 512];
    }
    __syncthreads();

    // ---- z partials: 8-deep LDG ring ----
    {
        int r  = w & 7;
        int kh = w >> 3;
        const float4* w1p = (const float4*)d_W1t + (size_t)kh * 256 * 32 + l;
        const float*  hrow = sm.hs[r] + kh * 256;
        float4 ring[8];
#pragma unroll
        for (int i = 0; i < 8; i++) ring[i] = w1p[(size_t)i * 32];
        float4 acc = make_float4(0.f, 0.f, 0.f, 0.f);
#pragma unroll 8
        for (int k = 0; k < 256; k++) {
            float4 cur = ring[k & 7];
            ring[k & 7] = w1p[(size_t)(k + 8) * 32];
            float hv = hrow[k];
            acc.x += hv * cur.x; acc.y += hv * cur.y;
            acc.z += hv * cur.z; acc.w += hv * cur.w;
        }
        *(float4*)&sm.zpart[w][4 * l] = acc;
    }
    __syncthreads();

    for (int idx = tid; idx < 8 * 128; idx += 512) {
        int r = idx >> 7, j = idx & 127;
        if (j < GPAD) {
            float v = 0.0f;
            if (j < GENn)
                v = fmaxf(sm.zpart[r][j] + sm.zpart[r + 8][j] + b1[j], 0.0f);
            sm.zs[j][r] = v;
        }
    }
    __syncthreads();

    // ---- logits ----
    float lg0[8], lg1[8];
#pragma unroll
    for (int r = 0; r < 8; r++) { lg0[r] = 0.f; lg1[r] = 0.f; }
    {
        const float2* w2p = (const float2*)d_W2t + w * 32 + l;
        float2 p0[4], p1[4];
#pragma unroll
        for (int i = 0; i < 4; i++) p0[i] = w2p[(size_t)i * 512];
#pragma unroll
        for (int i = 0; i < 4; i++) p1[i] = w2p[(size_t)(4 + i) * 512];
        for (int k0 = 0; k0 < GPAD; k0 += 4) {
            float2 nb[4];
#pragma unroll
            for (int i = 0; i < 4; i++) nb[i] = w2p[(size_t)(k0 + 8 + i) * 512];
#pragma unroll
            for (int i = 0; i < 4; i++) {
                int k = k0 + i;
                float zv[8];
                *(float4*)&zv[0] = *(const float4*)&sm.zs[k][0];
                *(float4*)&zv[4] = *(const float4*)&sm.zs[k][4];
#pragma unroll
                for (int r = 0; r < 8; r++) {
                    lg0[r] += p0[i].x * zv[r];
                    lg1[r] += p0[i].y * zv[r];
                }
            }
#pragma unroll
            for (int i = 0; i < 4; i++) { p0[i] = p1[i]; p1[i] = nb[i]; }
        }
        float bx = b2[w * 64 + 2 * l], by = b2[w * 64 + 2 * l + 1];
#pragma unroll
        for (int r = 0; r < 8; r++) { lg0[r] += bx; lg1[r] += by; }
    }

    int vbase = w * 64 + 2 * l;
#pragma unroll
    for (int r = 0; r < 8; r++) {
        float m; int a;
        if (lg1[r] > lg0[r]) { m = lg1[r]; a = vbase + 1; }
        else                 { m = lg0[r]; a = vbase;     }
#pragma unroll
        for (int o = 16; o > 0; o >>= 1) {
            float m2 = __shfl_xor_sync(0xffffffffu, m, o);
            int   a2 = __shfl_xor_sync(0xffffffffu, a, o);
            if (m2 > m || (m2 == m && a2 < a)) { m = m2; a = a2; }
        }
        if (l == 0) { sm.red[r][w] = m; sm.redi[r][w] = a; }
    }
    __syncthreads();

    if (tid < 8) {
        float m = sm.red[tid][0]; int a = sm.redi[tid][0];
#pragma unroll
        for (int ww = 1; ww < 16; ww++) {
            float m2 = sm.red[tid][ww]; int a2 = sm.redi[tid][ww];
            if (m2 > m || (m2 == m && a2 < a)) { m = m2; a = a2; }
        }
        d_tok[b0 + tid] = a;
        sm.gmaxS[tid] = m;
        __threadfence();                    // publish tok device-wide before counter bump
    }
    __syncthreads();
    if (tid == 0) atomicAdd(&d_ctr, 1u);    // release tok for co-resident gemm blocks

    float gmax[8];
#pragma unroll
    for (int r = 0; r < 8; r++) gmax[r] = sm.gmaxS[r];

#pragma unroll
    for (int r = 0; r < 8; r++) {
        float s = expf(lg0[r] - gmax[r]) + expf(lg1[r] - gmax[r]);
#pragma unroll
        for (int o = 16; o > 0; o >>= 1) s += __shfl_xor_sync(0xffffffffu, s, o);
        if (l == 0) sm.red[r][w] = s;
    }
    __syncthreads();

    float logZ[8];
#pragma unroll
    for (int r = 0; r < 8; r++) {
        float s = 0.0f;
#pragma unroll
        for (int ww = 0; ww < 16; ww++) s += sm.red[r][ww];
        logZ[r] = logf(s);
    }

#pragma unroll
    for (int r = 0; r < 8; r++) {
        float2 o2;
        o2.x = lg0[r] - gmax[r] - logZ[r];
        o2.y = lg1[r] - gmax[r] - logZ[r];
        *(float2*)&out[(size_t)(b0 + r) * Vn + vbase] = o2;
    }
}

// ---------------- fused: blocks 0-127 gemm+cell(t+1), blocks 128-255 head(t) ----------------
// launch_bounds(512,2): forces <=64 regs -> 2 CTAs/SM -> all 256 CTAs resident in one
// wave (296 slots) -> in-kernel producer-consumer sync is deadlock-free.
__global__ __launch_bounds__(512, 2) void fused_kernel(
    int nxt, int target,
    const float* __restrict__ b1,
    const float* __restrict__ b2,
    float* __restrict__ out) {
    __shared__ FusedSmem sm;
    if (blockIdx.x < 128) gemm_cell_body(sm.g, nxt, target, blockIdx.x);
    else                  head_body(sm.h, nxt, b1, b2, out, blockIdx.x - 128);
}

// ---------------- standalone wrappers (first gemm+cell, last head) ----------------
__global__ __launch_bounds__(512, 2) void gemm0_kernel(int nxt) {
    __shared__ GemmSmem sm;
    gemm_cell_body(sm, nxt, 0, blockIdx.x);     // target=0: tok ready from init
}
__global__ __launch_bounds__(512, 2) void head_kernel(
    int nxt,
    const float* __restrict__ b1,
    const float* __restrict__ b2,
    float* __restrict__ out) {
    __shared__ HeadSmem sm;
    head_body(sm, nxt, b1, b2, out, blockIdx.x);
}

// ---------------- launch: single stream, one fused kernel per step ----------------
extern "C" void kernel_launch(void* const* d_in, const int* in_sizes, int n_in,
                              void* d_out, int out_size) {
    (void)out_size;
    int off = (n_in >= 16 && in_sizes[3] == 1) ? 4 : 3;
    const float* input   = (const float*)d_in[0];
    const float* onehots = (const float*)d_in[1];
    const float* Wh   = (const float*)d_in[off + 0];
    const float* bh   = (const float*)d_in[off + 1];
    const float* Wc   = (const float*)d_in[off + 2];
    const float* bc   = (const float*)d_in[off + 3];
    const float* W_ih = (const float*)d_in[off + 4];
    const float* W_hh = (const float*)d_in[off + 5];
    const float* b_ih = (const float*)d_in[off + 6];
    const float* b_hh = (const float*)d_in[off + 7];
    const float* W1   = (const float*)d_in[off + 8];
    const float* b1   = (const float*)d_in[off + 9];
    const float* W2   = (const float*)d_in[off + 10];
    const float* b2   = (const float*)d_in[off + 11];
    float* out = (float*)d_out;

    const int prepN = Hn * 4 * Hn + W1ROWS * 128 + W2ROWS * Vn + Vn * 4 * Hn + 4 * Hn;
    prep_kernel<<<(prepN + 255) / 256, 256>>>(W_hh, W1, W2, W_ih, b_ih, b_hh);

    const int initN = Bn * Hn + Bn * Vn;
    init_kernel<<<(initN + 255) / 256, 256>>>(input, Wh, bh, Wc, bc, onehots);

    // t=0: gemm+cell over h_0 (tok_0 from init) -> h_1 in d_h[1]
    gemm0_kernel<<<128, 512>>>(0);

    // steps t=0..62: head_t (reads h_{t+1}, publishes tok_{t+1})
    //             || gemm+cell_{t+1} (reads h_{t+1}, waits tok_{t+1}, writes h_{t+2})
    for (int t = 0; t < Tn - 1; t++) {
        int nxt = (t + 1) & 1;
        fused_kernel<<<256, 512>>>(nxt, 128 * (t + 1), b1, b2, out + (size_t)t * Bn * Vn);
    }
    // final head_63 reads h_64 = d_h[0]
    head_kernel<<<128, 512>>>(Tn & 1, b1, b2, out + (size_t)(Tn - 1) * Bn * Vn);
}